// round 2
// baseline (speedup 1.0000x reference)
#include <cuda_runtime.h>

// GCN 2-layer, restructured to aggregate in 64-dim space on both layers:
//   dinv = rsqrt(1 + indeg)
//   xs   = x * dinv ;  agg1 = xs + scatter_add(xs[src] -> dst)
//   h1   = relu((agg1 * dinv) @ W1 + b1)
//   t    = h1 @ W2 ;  ts = t * dinv
//   agg2 = ts + scatter_add(ts[src] -> dst)
//   out  = agg2 * dinv + b2
// edge_index is int32 (JAX x64 disabled -> randint int64 request yields int32).

#define NMAX 100000
#define F 64
#define HID 128

__device__ float g_dinv[NMAX];
__device__ float g_xs[NMAX * F];
__device__ float g_agg[NMAX * F];
__device__ float g_h[NMAX * HID];

// ---------------------------------------------------------------- degree
__global__ void k_deg_init(int n) {
    int i = blockIdx.x * blockDim.x + threadIdx.x;
    if (i < n) g_dinv[i] = 1.0f;  // self loop
}

__global__ void k_deg_count(const int* __restrict__ dst, int E) {
    int i = blockIdx.x * blockDim.x + threadIdx.x;
    if (i < E) atomicAdd(&g_dinv[dst[i]], 1.0f);
}

__global__ void k_dinv(int n) {
    int i = blockIdx.x * blockDim.x + threadIdx.x;
    if (i < n) g_dinv[i] = rsqrtf(g_dinv[i]);
}

// xs = x * dinv; agg = xs (self-loop init). 16 float4 chunks per node row.
__global__ void k_scale_init(const float* __restrict__ x, int n) {
    int i = blockIdx.x * blockDim.x + threadIdx.x;
    if (i >= n * 16) return;
    int node = i >> 4;
    float dv = g_dinv[node];
    float4 v = ((const float4*)x)[i];
    v.x *= dv; v.y *= dv; v.z *= dv; v.w *= dv;
    ((float4*)g_xs)[i] = v;
    ((float4*)g_agg)[i] = v;
}

// ---------------------------------------------------------------- scatter
// 16 threads per edge; each handles one 16B chunk of the 256B feature row.
__global__ void k_scatter(const int* __restrict__ src,
                          const int* __restrict__ dst, int E) {
    int i = blockIdx.x * blockDim.x + threadIdx.x;
    if (i >= E * 16) return;
    int e = i >> 4;
    int c = i & 15;
    int s = __ldg(&src[e]);
    int d = __ldg(&dst[e]);
    float4 v = *(const float4*)(g_xs + (size_t)s * F + c * 4);
    float* p = g_agg + (size_t)d * F + c * 4;
    atomicAdd(p + 0, v.x);
    atomicAdd(p + 1, v.y);
    atomicAdd(p + 2, v.z);
    atomicAdd(p + 3, v.w);
}

// ---------------------------------------------------------------- layer 1
// Warp processes 4 nodes; per-warp transposed activation tile in shared.
// h1 = relu((agg1 * dinv) @ W1 + b1)  ->  g_h
#define L1_WARPS 8
#define L1_THREADS (L1_WARPS * 32)

__global__ void __launch_bounds__(L1_THREADS)
k_layer1(const float* __restrict__ W1, const float* __restrict__ b1, int n) {
    __shared__ __align__(16) float W1s[F * HID];          // 32 KB
    __shared__ __align__(16) float b1s[HID];
    __shared__ __align__(16) float aT[L1_WARPS][F * 4];   // 8 KB
    int tid = threadIdx.x;
    int warp = tid >> 5;
    int lane = tid & 31;

    for (int j = tid; j < F * HID; j += L1_THREADS) W1s[j] = W1[j];
    for (int j = tid; j < HID; j += L1_THREADS) b1s[j] = b1[j];
    __syncthreads();

    int nbase = (blockIdx.x * L1_WARPS + warp) * 4;
    if (nbase >= n) return;
    float* aTw = aT[warp];

#pragma unroll
    for (int ni = 0; ni < 4; ni++) {
        int node = nbase + ni;
        float a0 = 0.f, a1 = 0.f;
        if (node < n) {
            float dv = g_dinv[node];
            a0 = g_agg[(size_t)node * F + lane] * dv;
            a1 = g_agg[(size_t)node * F + 32 + lane] * dv;
        }
        aTw[lane * 4 + ni] = a0;
        aTw[(lane + 32) * 4 + ni] = a1;
    }
    __syncwarp();

    float acc[16];
#pragma unroll
    for (int q = 0; q < 16; q++) acc[q] = 0.f;
#pragma unroll 4
    for (int k = 0; k < F; k++) {
        float av0 = aTw[k * 4 + 0];
        float av1 = aTw[k * 4 + 1];
        float av2 = aTw[k * 4 + 2];
        float av3 = aTw[k * 4 + 3];
        float w0 = W1s[k * HID + lane];
        float w1 = W1s[k * HID + lane + 32];
        float w2 = W1s[k * HID + lane + 64];
        float w3 = W1s[k * HID + lane + 96];
        acc[0]  += av0 * w0;  acc[1]  += av0 * w1;  acc[2]  += av0 * w2;  acc[3]  += av0 * w3;
        acc[4]  += av1 * w0;  acc[5]  += av1 * w1;  acc[6]  += av1 * w2;  acc[7]  += av1 * w3;
        acc[8]  += av2 * w0;  acc[9]  += av2 * w1;  acc[10] += av2 * w2;  acc[11] += av2 * w3;
        acc[12] += av3 * w0;  acc[13] += av3 * w1;  acc[14] += av3 * w2;  acc[15] += av3 * w3;
    }
    float bb0 = b1s[lane], bb1 = b1s[lane + 32];
    float bb2 = b1s[lane + 64], bb3 = b1s[lane + 96];
#pragma unroll
    for (int ni = 0; ni < 4; ni++) {
        int node = nbase + ni;
        if (node < n) {
            float* hp = g_h + (size_t)node * HID;
            hp[lane]      = fmaxf(acc[ni * 4 + 0] + bb0, 0.f);
            hp[lane + 32] = fmaxf(acc[ni * 4 + 1] + bb1, 0.f);
            hp[lane + 64] = fmaxf(acc[ni * 4 + 2] + bb2, 0.f);
            hp[lane + 96] = fmaxf(acc[ni * 4 + 3] + bb3, 0.f);
        }
    }
}

// ---------------------------------------------------------------- layer 2
// t = h1 @ W2 ; ts = t * dinv -> g_xs (gather src) and g_agg (self-loop init)
#define L2_WARPS 4
#define L2_THREADS (L2_WARPS * 32)

__global__ void __launch_bounds__(L2_THREADS)
k_layer2(const float* __restrict__ W2, int n) {
    __shared__ __align__(16) float W2s[HID * F];           // 32 KB
    __shared__ __align__(16) float hT[L2_WARPS][HID * 4];  // 8 KB
    int tid = threadIdx.x;
    int warp = tid >> 5;
    int lane = tid & 31;

    for (int j = tid; j < HID * F; j += L2_THREADS) W2s[j] = W2[j];
    __syncthreads();

    int nbase = (blockIdx.x * L2_WARPS + warp) * 4;
    if (nbase >= n) return;
    float* hTw = hT[warp];

#pragma unroll
    for (int ni = 0; ni < 4; ni++) {
        int node = nbase + ni;
        float h0 = 0.f, h1 = 0.f, h2 = 0.f, h3 = 0.f;
        if (node < n) {
            const float* hp = g_h + (size_t)node * HID;
            h0 = hp[lane];
            h1 = hp[lane + 32];
            h2 = hp[lane + 64];
            h3 = hp[lane + 96];
        }
        hTw[lane * 4 + ni] = h0;
        hTw[(lane + 32) * 4 + ni] = h1;
        hTw[(lane + 64) * 4 + ni] = h2;
        hTw[(lane + 96) * 4 + ni] = h3;
    }
    __syncwarp();

    float t0[4] = {0.f, 0.f, 0.f, 0.f};
    float t1[4] = {0.f, 0.f, 0.f, 0.f};
#pragma unroll 4
    for (int k = 0; k < HID; k++) {
        float hv0 = hTw[k * 4 + 0];
        float hv1 = hTw[k * 4 + 1];
        float hv2 = hTw[k * 4 + 2];
        float hv3 = hTw[k * 4 + 3];
        float u0 = W2s[k * F + lane];
        float u1 = W2s[k * F + lane + 32];
        t0[0] += hv0 * u0;  t1[0] += hv0 * u1;
        t0[1] += hv1 * u0;  t1[1] += hv1 * u1;
        t0[2] += hv2 * u0;  t1[2] += hv2 * u1;
        t0[3] += hv3 * u0;  t1[3] += hv3 * u1;
    }

#pragma unroll
    for (int ni = 0; ni < 4; ni++) {
        int node = nbase + ni;
        if (node < n) {
            float dv = g_dinv[node];
            float v0 = t0[ni] * dv;
            float v1 = t1[ni] * dv;
            g_xs[(size_t)node * F + lane] = v0;
            g_xs[(size_t)node * F + 32 + lane] = v1;
            g_agg[(size_t)node * F + lane] = v0;
            g_agg[(size_t)node * F + 32 + lane] = v1;
        }
    }
}

// ---------------------------------------------------------------- epilogue
__global__ void k_out(const float* __restrict__ b2, float* __restrict__ out, int n) {
    int i = blockIdx.x * blockDim.x + threadIdx.x;
    if (i >= n * 16) return;
    int node = i >> 4;
    int c = i & 15;
    float dv = g_dinv[node];
    float4 v = ((const float4*)g_agg)[i];
    float4 b = ((const float4*)b2)[c];
    v.x = v.x * dv + b.x;
    v.y = v.y * dv + b.y;
    v.z = v.z * dv + b.z;
    v.w = v.w * dv + b.w;
    ((float4*)out)[i] = v;
}

// ---------------------------------------------------------------- launch
extern "C" void kernel_launch(void* const* d_in, const int* in_sizes, int n_in,
                              void* d_out, int out_size) {
    const float* x  = (const float*)d_in[0];
    const int* ei   = (const int*)d_in[1];   // int32 edge_index [2, E]
    const float* W1 = (const float*)d_in[2];
    const float* b1 = (const float*)d_in[3];
    const float* W2 = (const float*)d_in[4];
    const float* b2 = (const float*)d_in[5];
    float* out      = (float*)d_out;

    int n = in_sizes[0] / F;   // 100000
    int E = in_sizes[1] / 2;   // 1600000
    const int* src = ei;
    const int* dst = ei + E;

    int nb256 = (n + 255) / 256;
    k_deg_init<<<nb256, 256>>>(n);
    k_deg_count<<<(E + 255) / 256, 256>>>(dst, E);
    k_dinv<<<nb256, 256>>>(n);
    k_scale_init<<<(n * 16 + 255) / 256, 256>>>(x, n);

    int scat_blocks = (E * 16 + 255) / 256;
    k_scatter<<<scat_blocks, 256>>>(src, dst, E);

    int warps_needed = (n + 3) / 4;
    k_layer1<<<(warps_needed + L1_WARPS - 1) / L1_WARPS, L1_THREADS>>>(W1, b1, n);
    k_layer2<<<(warps_needed + L2_WARPS - 1) / L2_WARPS, L2_THREADS>>>(W2, n);

    k_scatter<<<scat_blocks, 256>>>(src, dst, E);

    k_out<<<(n * 16 + 255) / 256, 256>>>(b2, out, n);
}

// round 3
// speedup vs baseline: 1.6541x; 1.6541x over previous
#include <cuda_runtime.h>

// GCN 2-layer, aggregate-in-64-dim on both layers:
//   dinv = rsqrt(1 + indeg)
//   xs   = x * dinv ;  agg1 = xs + scatter_add(xs[src] -> dst)
//   h1   = relu((agg1 * dinv) @ W1 + b1)
//   t    = h1 @ W2 ;  ts = t * dinv
//   agg2 = ts + scatter_add(ts[src] -> dst)
//   out  = agg2 * dinv + b2
// edge_index is int32. Scatter uses red.global.add.v4.f32 (sm_90+).

#define NMAX 100000
#define F 64
#define HID 128

__device__ float g_dinv[NMAX];
__device__ float g_xs[NMAX * F];
__device__ float g_agg[NMAX * F];
__device__ float g_h[NMAX * HID];

// ---------------------------------------------------------------- degree
__global__ void k_deg_init(int n) {
    int i = blockIdx.x * blockDim.x + threadIdx.x;
    if (i < n) g_dinv[i] = 1.0f;  // self loop
}

__global__ void k_deg_count(const int* __restrict__ dst, int E) {
    int i = blockIdx.x * blockDim.x + threadIdx.x;
    if (i < E) atomicAdd(&g_dinv[dst[i]], 1.0f);
}

__global__ void k_dinv(int n) {
    int i = blockIdx.x * blockDim.x + threadIdx.x;
    if (i < n) g_dinv[i] = rsqrtf(g_dinv[i]);
}

// xs = x * dinv; agg = xs (self-loop init). 16 float4 chunks per node row.
__global__ void k_scale_init(const float* __restrict__ x, int n) {
    int i = blockIdx.x * blockDim.x + threadIdx.x;
    if (i >= n * 16) return;
    int node = i >> 4;
    float dv = g_dinv[node];
    float4 v = ((const float4*)x)[i];
    v.x *= dv; v.y *= dv; v.z *= dv; v.w *= dv;
    ((float4*)g_xs)[i] = v;
    ((float4*)g_agg)[i] = v;
}

// ---------------------------------------------------------------- scatter
// 16 threads per edge; each handles one 16B chunk of the 256B feature row.
// One red.global.add.v4.f32 per chunk (4x fewer RED ops than scalar).
__global__ void k_scatter(const int* __restrict__ src,
                          const int* __restrict__ dst, int E) {
    int i = blockIdx.x * blockDim.x + threadIdx.x;
    if (i >= E * 16) return;
    int e = i >> 4;
    int c = i & 15;
    int s = __ldg(&src[e]);
    int d = __ldg(&dst[e]);
    float4 v = *(const float4*)(g_xs + (size_t)s * F + c * 4);
    float* p = g_agg + (size_t)d * F + c * 4;
    asm volatile("red.global.add.v4.f32 [%0], {%1, %2, %3, %4};"
                 :: "l"(p), "f"(v.x), "f"(v.y), "f"(v.z), "f"(v.w)
                 : "memory");
}

// ---------------------------------------------------------------- layer 1
// Warp processes 4 nodes; per-warp transposed activation tile in shared.
// h1 = relu((agg1 * dinv) @ W1 + b1)  ->  g_h
#define L1_WARPS 8
#define L1_THREADS (L1_WARPS * 32)

__global__ void __launch_bounds__(L1_THREADS)
k_layer1(const float* __restrict__ W1, const float* __restrict__ b1, int n) {
    __shared__ __align__(16) float W1s[F * HID];          // 32 KB
    __shared__ __align__(16) float b1s[HID];
    __shared__ __align__(16) float aT[L1_WARPS][F * 4];   // 8 KB
    int tid = threadIdx.x;
    int warp = tid >> 5;
    int lane = tid & 31;

    for (int j = tid; j < F * HID; j += L1_THREADS) W1s[j] = W1[j];
    for (int j = tid; j < HID; j += L1_THREADS) b1s[j] = b1[j];
    __syncthreads();

    int nbase = (blockIdx.x * L1_WARPS + warp) * 4;
    if (nbase >= n) return;
    float* aTw = aT[warp];

#pragma unroll
    for (int ni = 0; ni < 4; ni++) {
        int node = nbase + ni;
        float a0 = 0.f, a1 = 0.f;
        if (node < n) {
            float dv = g_dinv[node];
            a0 = g_agg[(size_t)node * F + lane] * dv;
            a1 = g_agg[(size_t)node * F + 32 + lane] * dv;
        }
        aTw[lane * 4 + ni] = a0;
        aTw[(lane + 32) * 4 + ni] = a1;
    }
    __syncwarp();

    float acc[16];
#pragma unroll
    for (int q = 0; q < 16; q++) acc[q] = 0.f;
#pragma unroll 4
    for (int k = 0; k < F; k++) {
        float av0 = aTw[k * 4 + 0];
        float av1 = aTw[k * 4 + 1];
        float av2 = aTw[k * 4 + 2];
        float av3 = aTw[k * 4 + 3];
        float w0 = W1s[k * HID + lane];
        float w1 = W1s[k * HID + lane + 32];
        float w2 = W1s[k * HID + lane + 64];
        float w3 = W1s[k * HID + lane + 96];
        acc[0]  += av0 * w0;  acc[1]  += av0 * w1;  acc[2]  += av0 * w2;  acc[3]  += av0 * w3;
        acc[4]  += av1 * w0;  acc[5]  += av1 * w1;  acc[6]  += av1 * w2;  acc[7]  += av1 * w3;
        acc[8]  += av2 * w0;  acc[9]  += av2 * w1;  acc[10] += av2 * w2;  acc[11] += av2 * w3;
        acc[12] += av3 * w0;  acc[13] += av3 * w1;  acc[14] += av3 * w2;  acc[15] += av3 * w3;
    }
    float bb0 = b1s[lane], bb1 = b1s[lane + 32];
    float bb2 = b1s[lane + 64], bb3 = b1s[lane + 96];
#pragma unroll
    for (int ni = 0; ni < 4; ni++) {
        int node = nbase + ni;
        if (node < n) {
            float* hp = g_h + (size_t)node * HID;
            hp[lane]      = fmaxf(acc[ni * 4 + 0] + bb0, 0.f);
            hp[lane + 32] = fmaxf(acc[ni * 4 + 1] + bb1, 0.f);
            hp[lane + 64] = fmaxf(acc[ni * 4 + 2] + bb2, 0.f);
            hp[lane + 96] = fmaxf(acc[ni * 4 + 3] + bb3, 0.f);
        }
    }
}

// ---------------------------------------------------------------- layer 2
// t = h1 @ W2 ; ts = t * dinv -> g_xs (gather src) and g_agg (self-loop init)
#define L2_WARPS 4
#define L2_THREADS (L2_WARPS * 32)

__global__ void __launch_bounds__(L2_THREADS)
k_layer2(const float* __restrict__ W2, int n) {
    __shared__ __align__(16) float W2s[HID * F];           // 32 KB
    __shared__ __align__(16) float hT[L2_WARPS][HID * 4];  // 8 KB
    int tid = threadIdx.x;
    int warp = tid >> 5;
    int lane = tid & 31;

    for (int j = tid; j < HID * F; j += L2_THREADS) W2s[j] = W2[j];
    __syncthreads();

    int nbase = (blockIdx.x * L2_WARPS + warp) * 4;
    if (nbase >= n) return;
    float* hTw = hT[warp];

#pragma unroll
    for (int ni = 0; ni < 4; ni++) {
        int node = nbase + ni;
        float h0 = 0.f, h1 = 0.f, h2 = 0.f, h3 = 0.f;
        if (node < n) {
            const float* hp = g_h + (size_t)node * HID;
            h0 = hp[lane];
            h1 = hp[lane + 32];
            h2 = hp[lane + 64];
            h3 = hp[lane + 96];
        }
        hTw[lane * 4 + ni] = h0;
        hTw[(lane + 32) * 4 + ni] = h1;
        hTw[(lane + 64) * 4 + ni] = h2;
        hTw[(lane + 96) * 4 + ni] = h3;
    }
    __syncwarp();

    float t0[4] = {0.f, 0.f, 0.f, 0.f};
    float t1[4] = {0.f, 0.f, 0.f, 0.f};
#pragma unroll 4
    for (int k = 0; k < HID; k++) {
        float hv0 = hTw[k * 4 + 0];
        float hv1 = hTw[k * 4 + 1];
        float hv2 = hTw[k * 4 + 2];
        float hv3 = hTw[k * 4 + 3];
        float u0 = W2s[k * F + lane];
        float u1 = W2s[k * F + lane + 32];
        t0[0] += hv0 * u0;  t1[0] += hv0 * u1;
        t0[1] += hv1 * u0;  t1[1] += hv1 * u1;
        t0[2] += hv2 * u0;  t1[2] += hv2 * u1;
        t0[3] += hv3 * u0;  t1[3] += hv3 * u1;
    }

#pragma unroll
    for (int ni = 0; ni < 4; ni++) {
        int node = nbase + ni;
        if (node < n) {
            float dv = g_dinv[node];
            float v0 = t0[ni] * dv;
            float v1 = t1[ni] * dv;
            g_xs[(size_t)node * F + lane] = v0;
            g_xs[(size_t)node * F + 32 + lane] = v1;
            g_agg[(size_t)node * F + lane] = v0;
            g_agg[(size_t)node * F + 32 + lane] = v1;
        }
    }
}

// ---------------------------------------------------------------- epilogue
__global__ void k_out(const float* __restrict__ b2, float* __restrict__ out, int n) {
    int i = blockIdx.x * blockDim.x + threadIdx.x;
    if (i >= n * 16) return;
    int node = i >> 4;
    int c = i & 15;
    float dv = g_dinv[node];
    float4 v = ((const float4*)g_agg)[i];
    float4 b = ((const float4*)b2)[c];
    v.x = v.x * dv + b.x;
    v.y = v.y * dv + b.y;
    v.z = v.z * dv + b.z;
    v.w = v.w * dv + b.w;
    ((float4*)out)[i] = v;
}

// ---------------------------------------------------------------- launch
extern "C" void kernel_launch(void* const* d_in, const int* in_sizes, int n_in,
                              void* d_out, int out_size) {
    const float* x  = (const float*)d_in[0];
    const int* ei   = (const int*)d_in[1];   // int32 edge_index [2, E]
    const float* W1 = (const float*)d_in[2];
    const float* b1 = (const float*)d_in[3];
    const float* W2 = (const float*)d_in[4];
    const float* b2 = (const float*)d_in[5];
    float* out      = (float*)d_out;

    int n = in_sizes[0] / F;   // 100000
    int E = in_sizes[1] / 2;   // 1600000
    const int* src = ei;
    const int* dst = ei + E;

    int nb256 = (n + 255) / 256;
    k_deg_init<<<nb256, 256>>>(n);
    k_deg_count<<<(E + 255) / 256, 256>>>(dst, E);
    k_dinv<<<nb256, 256>>>(n);
    k_scale_init<<<(n * 16 + 255) / 256, 256>>>(x, n);

    int scat_blocks = (E * 16 + 255) / 256;
    k_scatter<<<scat_blocks, 256>>>(src, dst, E);

    int warps_needed = (n + 3) / 4;
    k_layer1<<<(warps_needed + L1_WARPS - 1) / L1_WARPS, L1_THREADS>>>(W1, b1, n);
    k_layer2<<<(warps_needed + L2_WARPS - 1) / L2_WARPS, L2_THREADS>>>(W2, n);

    k_scatter<<<scat_blocks, 256>>>(src, dst, E);

    k_out<<<(n * 16 + 255) / 256, 256>>>(b2, out, n);
}

// round 4
// speedup vs baseline: 2.3152x; 1.3997x over previous
#include <cuda_runtime.h>

// GCN 2-layer, aggregate-in-64-dim on both layers, CSR-gather aggregation:
//   count = indegree (histogram);  dinv = rsqrt(1 + count)
//   CSR: row_ptr = exscan(count);  csr_src = edges permuted by dst
//   xs   = x * dinv
//   a    = (xs[d] + sum_{src in N(d)} xs[src]) * dinv[d]        (gather1 -> g_agg)
//   h1   = relu(a @ W1 + b1)                                     (layer1 -> g_h)
//   ts   = (h1 @ W2) * dinv                                      (layer2 -> g_xs)
//   out  = (ts[d] + sum ts[src]) * dinv[d] + b2                  (gather2 -> out)
// edge_index is int32.

#define NMAX 100000
#define EMAX 1600000
#define F 64
#define HID 128
#define SCAN_BS 1024
#define SCAN_NB ((NMAX + SCAN_BS - 1) / SCAN_BS)   // 98

__device__ float g_dinv[NMAX];
__device__ float g_xs[NMAX * F];
__device__ float g_agg[NMAX * F];
__device__ float g_h[NMAX * HID];

__device__ int g_count[NMAX];
__device__ int g_excl[NMAX];
__device__ int g_row_ptr[NMAX + 1];
__device__ int g_cursor[NMAX];
__device__ int g_bsum[SCAN_NB];
__device__ int g_boff[SCAN_NB];
__device__ int g_csr[EMAX];

// ---------------------------------------------------------------- CSR build
__global__ void k_zero(int n) {
    int i = blockIdx.x * blockDim.x + threadIdx.x;
    if (i < n) g_count[i] = 0;
}

__global__ void k_hist(const int* __restrict__ dst, int E) {
    int i = blockIdx.x * blockDim.x + threadIdx.x;
    if (i < E) atomicAdd(&g_count[dst[i]], 1);
}

__global__ void k_scan1(int n) {
    __shared__ int sm[SCAN_BS];
    int tid = threadIdx.x;
    int i = blockIdx.x * SCAN_BS + tid;
    int v = (i < n) ? g_count[i] : 0;
    sm[tid] = v;
    __syncthreads();
    for (int off = 1; off < SCAN_BS; off <<= 1) {
        int t = (tid >= off) ? sm[tid - off] : 0;
        __syncthreads();
        sm[tid] += t;
        __syncthreads();
    }
    if (i < n) g_excl[i] = sm[tid] - v;
    if (tid == SCAN_BS - 1) g_bsum[blockIdx.x] = sm[tid];
}

__global__ void k_scan2(int nb) {
    __shared__ int sm[SCAN_NB];
    int t = threadIdx.x;
    if (t < nb) sm[t] = g_bsum[t];
    __syncthreads();
    if (t == 0) {
        int run = 0;
        for (int j = 0; j < nb; j++) { int v = sm[j]; sm[j] = run; run += v; }
    }
    __syncthreads();
    if (t < nb) g_boff[t] = sm[t];
}

__global__ void k_scan3(int n, int E) {
    int i = blockIdx.x * blockDim.x + threadIdx.x;
    if (i < n) {
        int r = g_excl[i] + g_boff[i / SCAN_BS];
        g_row_ptr[i] = r;
        g_cursor[i] = r;
        if (i == 0) g_row_ptr[n] = E;
    }
}

__global__ void k_permute(const int* __restrict__ src,
                          const int* __restrict__ dst, int E) {
    int i = blockIdx.x * blockDim.x + threadIdx.x;
    if (i < E) {
        int pos = atomicAdd(&g_cursor[dst[i]], 1);
        g_csr[pos] = src[i];
    }
}

// ---------------------------------------------------------------- prep
__global__ void k_dinv(int n) {
    int i = blockIdx.x * blockDim.x + threadIdx.x;
    if (i < n) g_dinv[i] = rsqrtf(1.0f + (float)g_count[i]);
}

// xs = x * dinv.  16 float4 chunks per node row.
__global__ void k_scale(const float* __restrict__ x, int n) {
    int i = blockIdx.x * blockDim.x + threadIdx.x;
    if (i >= n * 16) return;
    int node = i >> 4;
    float dv = g_dinv[node];
    float4 v = ((const float4*)x)[i];
    v.x *= dv; v.y *= dv; v.z *= dv; v.w *= dv;
    ((float4*)g_xs)[i] = v;
}

// ---------------------------------------------------------------- gathers
// 16 threads per dst node; thread owns one 16B chunk.  Unroll-4 for MLP.
__device__ __forceinline__ float4 gather_row(int d, int c) {
    const float4* base = (const float4*)g_xs;
    float4 acc = base[d * 16 + c];             // self loop
    int e = g_row_ptr[d];
    int end = g_row_ptr[d + 1];
    for (; e + 4 <= end; e += 4) {
        int s0 = __ldg(&g_csr[e + 0]);
        int s1 = __ldg(&g_csr[e + 1]);
        int s2 = __ldg(&g_csr[e + 2]);
        int s3 = __ldg(&g_csr[e + 3]);
        float4 v0 = base[s0 * 16 + c];
        float4 v1 = base[s1 * 16 + c];
        float4 v2 = base[s2 * 16 + c];
        float4 v3 = base[s3 * 16 + c];
        acc.x += (v0.x + v1.x) + (v2.x + v3.x);
        acc.y += (v0.y + v1.y) + (v2.y + v3.y);
        acc.z += (v0.z + v1.z) + (v2.z + v3.z);
        acc.w += (v0.w + v1.w) + (v2.w + v3.w);
    }
    for (; e < end; e++) {
        int s = __ldg(&g_csr[e]);
        float4 v = base[s * 16 + c];
        acc.x += v.x; acc.y += v.y; acc.z += v.z; acc.w += v.w;
    }
    return acc;
}

// gather1: g_agg = (xs[d] + sum xs[src]) * dinv[d]   (pre-scaled 'a')
__global__ void k_gather1(int n) {
    int i = blockIdx.x * blockDim.x + threadIdx.x;
    if (i >= n * 16) return;
    int d = i >> 4, c = i & 15;
    float4 acc = gather_row(d, c);
    float dv = g_dinv[d];
    acc.x *= dv; acc.y *= dv; acc.z *= dv; acc.w *= dv;
    ((float4*)g_agg)[i] = acc;
}

// gather2 + epilogue: out = (ts[d] + sum ts[src]) * dinv[d] + b2
__global__ void k_gather2(const float* __restrict__ b2,
                          float* __restrict__ out, int n) {
    int i = blockIdx.x * blockDim.x + threadIdx.x;
    if (i >= n * 16) return;
    int d = i >> 4, c = i & 15;
    float4 acc = gather_row(d, c);
    float dv = g_dinv[d];
    float4 b = ((const float4*)b2)[c];
    acc.x = acc.x * dv + b.x;
    acc.y = acc.y * dv + b.y;
    acc.z = acc.z * dv + b.z;
    acc.w = acc.w * dv + b.w;
    ((float4*)out)[i] = acc;
}

// ---------------------------------------------------------------- layer 1
// Warp processes 4 nodes; per-warp transposed activation tile in shared.
// h1 = relu(a @ W1 + b1)  ->  g_h    (a = g_agg, already dinv-scaled)
#define L1_WARPS 8
#define L1_THREADS (L1_WARPS * 32)

__global__ void __launch_bounds__(L1_THREADS)
k_layer1(const float* __restrict__ W1, const float* __restrict__ b1, int n) {
    __shared__ __align__(16) float W1s[F * HID];          // 32 KB
    __shared__ __align__(16) float b1s[HID];
    __shared__ __align__(16) float aT[L1_WARPS][F * 4];   // 8 KB
    int tid = threadIdx.x;
    int warp = tid >> 5;
    int lane = tid & 31;

    for (int j = tid; j < F * HID; j += L1_THREADS) W1s[j] = W1[j];
    for (int j = tid; j < HID; j += L1_THREADS) b1s[j] = b1[j];
    __syncthreads();

    int nbase = (blockIdx.x * L1_WARPS + warp) * 4;
    if (nbase >= n) return;
    float* aTw = aT[warp];

#pragma unroll
    for (int ni = 0; ni < 4; ni++) {
        int node = nbase + ni;
        float a0 = 0.f, a1 = 0.f;
        if (node < n) {
            a0 = g_agg[(size_t)node * F + lane];
            a1 = g_agg[(size_t)node * F + 32 + lane];
        }
        aTw[lane * 4 + ni] = a0;
        aTw[(lane + 32) * 4 + ni] = a1;
    }
    __syncwarp();

    float acc[16];
#pragma unroll
    for (int q = 0; q < 16; q++) acc[q] = 0.f;
#pragma unroll 4
    for (int k = 0; k < F; k++) {
        float av0 = aTw[k * 4 + 0];
        float av1 = aTw[k * 4 + 1];
        float av2 = aTw[k * 4 + 2];
        float av3 = aTw[k * 4 + 3];
        float w0 = W1s[k * HID + lane];
        float w1 = W1s[k * HID + lane + 32];
        float w2 = W1s[k * HID + lane + 64];
        float w3 = W1s[k * HID + lane + 96];
        acc[0]  += av0 * w0;  acc[1]  += av0 * w1;  acc[2]  += av0 * w2;  acc[3]  += av0 * w3;
        acc[4]  += av1 * w0;  acc[5]  += av1 * w1;  acc[6]  += av1 * w2;  acc[7]  += av1 * w3;
        acc[8]  += av2 * w0;  acc[9]  += av2 * w1;  acc[10] += av2 * w2;  acc[11] += av2 * w3;
        acc[12] += av3 * w0;  acc[13] += av3 * w1;  acc[14] += av3 * w2;  acc[15] += av3 * w3;
    }
    float bb0 = b1s[lane], bb1 = b1s[lane + 32];
    float bb2 = b1s[lane + 64], bb3 = b1s[lane + 96];
#pragma unroll
    for (int ni = 0; ni < 4; ni++) {
        int node = nbase + ni;
        if (node < n) {
            float* hp = g_h + (size_t)node * HID;
            hp[lane]      = fmaxf(acc[ni * 4 + 0] + bb0, 0.f);
            hp[lane + 32] = fmaxf(acc[ni * 4 + 1] + bb1, 0.f);
            hp[lane + 64] = fmaxf(acc[ni * 4 + 2] + bb2, 0.f);
            hp[lane + 96] = fmaxf(acc[ni * 4 + 3] + bb3, 0.f);
        }
    }
}

// ---------------------------------------------------------------- layer 2
// ts = (h1 @ W2) * dinv -> g_xs (gather2 source)
#define L2_WARPS 4
#define L2_THREADS (L2_WARPS * 32)

__global__ void __launch_bounds__(L2_THREADS)
k_layer2(const float* __restrict__ W2, int n) {
    __shared__ __align__(16) float W2s[HID * F];           // 32 KB
    __shared__ __align__(16) float hT[L2_WARPS][HID * 4];  // 8 KB
    int tid = threadIdx.x;
    int warp = tid >> 5;
    int lane = tid & 31;

    for (int j = tid; j < HID * F; j += L2_THREADS) W2s[j] = W2[j];
    __syncthreads();

    int nbase = (blockIdx.x * L2_WARPS + warp) * 4;
    if (nbase >= n) return;
    float* hTw = hT[warp];

#pragma unroll
    for (int ni = 0; ni < 4; ni++) {
        int node = nbase + ni;
        float h0 = 0.f, h1 = 0.f, h2 = 0.f, h3 = 0.f;
        if (node < n) {
            const float* hp = g_h + (size_t)node * HID;
            h0 = hp[lane];
            h1 = hp[lane + 32];
            h2 = hp[lane + 64];
            h3 = hp[lane + 96];
        }
        hTw[lane * 4 + ni] = h0;
        hTw[(lane + 32) * 4 + ni] = h1;
        hTw[(lane + 64) * 4 + ni] = h2;
        hTw[(lane + 96) * 4 + ni] = h3;
    }
    __syncwarp();

    float t0[4] = {0.f, 0.f, 0.f, 0.f};
    float t1[4] = {0.f, 0.f, 0.f, 0.f};
#pragma unroll 4
    for (int k = 0; k < HID; k++) {
        float hv0 = hTw[k * 4 + 0];
        float hv1 = hTw[k * 4 + 1];
        float hv2 = hTw[k * 4 + 2];
        float hv3 = hTw[k * 4 + 3];
        float u0 = W2s[k * F + lane];
        float u1 = W2s[k * F + lane + 32];
        t0[0] += hv0 * u0;  t1[0] += hv0 * u1;
        t0[1] += hv1 * u0;  t1[1] += hv1 * u1;
        t0[2] += hv2 * u0;  t1[2] += hv2 * u1;
        t0[3] += hv3 * u0;  t1[3] += hv3 * u1;
    }

#pragma unroll
    for (int ni = 0; ni < 4; ni++) {
        int node = nbase + ni;
        if (node < n) {
            float dv = g_dinv[node];
            g_xs[(size_t)node * F + lane]      = t0[ni] * dv;
            g_xs[(size_t)node * F + 32 + lane] = t1[ni] * dv;
        }
    }
}

// ---------------------------------------------------------------- launch
extern "C" void kernel_launch(void* const* d_in, const int* in_sizes, int n_in,
                              void* d_out, int out_size) {
    const float* x  = (const float*)d_in[0];
    const int* ei   = (const int*)d_in[1];   // int32 edge_index [2, E]
    const float* W1 = (const float*)d_in[2];
    const float* b1 = (const float*)d_in[3];
    const float* W2 = (const float*)d_in[4];
    const float* b2 = (const float*)d_in[5];
    float* out      = (float*)d_out;

    int n = in_sizes[0] / F;   // 100000
    int E = in_sizes[1] / 2;   // 1600000
    const int* src = ei;
    const int* dst = ei + E;

    int nbN = (n + 255) / 256;
    int nbE = (E + 255) / 256;
    int nb16 = (n * 16 + 255) / 256;
    int nbScan = (n + SCAN_BS - 1) / SCAN_BS;

    // CSR build + degree
    k_zero<<<nbN, 256>>>(n);
    k_hist<<<nbE, 256>>>(dst, E);
    k_scan1<<<nbScan, SCAN_BS>>>(n);
    k_scan2<<<1, SCAN_NB>>>(nbScan);
    k_scan3<<<nbN, 256>>>(n, E);
    k_permute<<<nbE, 256>>>(src, dst, E);
    k_dinv<<<nbN, 256>>>(n);

    // layer 1
    k_scale<<<nb16, 256>>>(x, n);
    k_gather1<<<nb16, 256>>>(n);

    int warps_needed = (n + 3) / 4;
    k_layer1<<<(warps_needed + L1_WARPS - 1) / L1_WARPS, L1_THREADS>>>(W1, b1, n);
    k_layer2<<<(warps_needed + L2_WARPS - 1) / L2_WARPS, L2_THREADS>>>(W2, n);

    // layer 2 aggregation + epilogue
    k_gather2<<<nb16, 256>>>(b2, out, n);
}

// round 6
// speedup vs baseline: 2.5770x; 1.1131x over previous
#include <cuda_runtime.h>

// GCN 2-layer, CSR-gather aggregation, fused FFMA2 double-GEMM:
//   count = indegree;  dinv = rsqrt(1 + count);  CSR by dst
//   a    = (x[d]*dinv[d] + sum x[s]*dinv[s]) * dinv[d]     (gather1 -> g_agg)
//   h1   = relu(a @ W1 + b1)   }  one fused kernel, h1 kept in smem
//   ts   = (h1 @ W2) * dinv    }                            (-> g_ts)
//   out  = (ts[d] + sum ts[s]) * dinv[d] + b2               (gather2 -> out)
// edge_index is int32.
// NOTE: device symbols are only referenced from device code (ATS on GB300
// makes host-side symbol addresses silently "work" on host memory).

#define NMAX 100000
#define EMAX 1600000
#define F 64
#define HID 128
#define SCAN_BS 1024
#define SCAN_NB ((NMAX + SCAN_BS - 1) / SCAN_BS)   // 98

typedef unsigned long long ull;

__device__ float g_dinv[NMAX];
__device__ float g_agg[NMAX * F];
__device__ float g_ts[NMAX * F];

__device__ int g_count[NMAX];
__device__ int g_excl[NMAX];
__device__ int g_row_ptr[NMAX + 1];
__device__ int g_cursor[NMAX];
__device__ int g_bsum[SCAN_NB];
__device__ int g_boff[SCAN_NB];
__device__ int g_csr[EMAX];

// ---------------------------------------------------------------- f32x2 helpers
__device__ __forceinline__ ull pack2(float lo, float hi) {
    ull r;
    asm("mov.b64 %0, {%1, %2};" : "=l"(r) : "f"(lo), "f"(hi));
    return r;
}
__device__ __forceinline__ void unpack2(ull v, float& lo, float& hi) {
    asm("mov.b64 {%0, %1}, %2;" : "=f"(lo), "=f"(hi) : "l"(v));
}
__device__ __forceinline__ ull ffma2(ull a, ull b, ull c) {
    ull d;
    asm("fma.rn.f32x2 %0, %1, %2, %3;" : "=l"(d) : "l"(a), "l"(b), "l"(c));
    return d;
}

// ---------------------------------------------------------------- CSR build
__global__ void k_zero(int n) {
    int i = blockIdx.x * blockDim.x + threadIdx.x;
    if (i < n) g_count[i] = 0;
}

__global__ void k_hist(const int* __restrict__ dst, int E) {
    int i = blockIdx.x * blockDim.x + threadIdx.x;
    if (i < E) atomicAdd(&g_count[dst[i]], 1);
}

__global__ void k_scan1(int n) {
    __shared__ int sm[SCAN_BS];
    int tid = threadIdx.x;
    int i = blockIdx.x * SCAN_BS + tid;
    int v = (i < n) ? g_count[i] : 0;
    sm[tid] = v;
    __syncthreads();
    for (int off = 1; off < SCAN_BS; off <<= 1) {
        int t = (tid >= off) ? sm[tid - off] : 0;
        __syncthreads();
        sm[tid] += t;
        __syncthreads();
    }
    if (i < n) g_excl[i] = sm[tid] - v;
    if (tid == SCAN_BS - 1) g_bsum[blockIdx.x] = sm[tid];
}

__global__ void k_scan2(int nb) {
    __shared__ int sm[128];
    int t = threadIdx.x;
    int v = (t < nb) ? g_bsum[t] : 0;
    sm[t] = v;
    __syncthreads();
    for (int off = 1; off < 128; off <<= 1) {
        int u = (t >= off) ? sm[t - off] : 0;
        __syncthreads();
        sm[t] += u;
        __syncthreads();
    }
    if (t < nb) g_boff[t] = sm[t] - v;   // exclusive
}

__global__ void k_scan3(int n, int E) {
    int i = blockIdx.x * blockDim.x + threadIdx.x;
    if (i < n) {
        int r = g_excl[i] + g_boff[i / SCAN_BS];
        g_row_ptr[i] = r;
        g_cursor[i] = r;
        g_dinv[i] = rsqrtf(1.0f + (float)g_count[i]);
        if (i == 0) g_row_ptr[n] = E;
    }
}

__global__ void k_permute(const int* __restrict__ src,
                          const int* __restrict__ dst, int E) {
    int i = blockIdx.x * blockDim.x + threadIdx.x;
    if (i < E) {
        int pos = atomicAdd(&g_cursor[dst[i]], 1);
        g_csr[pos] = src[i];
    }
}

// ---------------------------------------------------------------- gathers
// One warp per dst node. Lanes 0-15: chunk c over even edges; lanes 16-31:
// chunk c over odd edges. Halves merged via shfl_down(16). Uniform trip
// count within the warp.
// MODE 0 (layer1): source = x (param), neighbor rows scaled by dinv[s];
//                  result *= dinv[d]; write g_agg (device symbol).
// MODE 1 (layer2): source = g_ts (device symbol, pre-scaled);
//                  result = acc*dinv[d] + b2 -> out (param).
template <int MODE>
__global__ void __launch_bounds__(256)
k_gather(const float* __restrict__ xparam, const float* __restrict__ b2,
         float* __restrict__ outparam, int n) {
    int gwarp = (blockIdx.x * blockDim.x + threadIdx.x) >> 5;
    if (gwarp >= n) return;
    int lane = threadIdx.x & 31;
    int d = gwarp;
    int c = lane & 15;
    int half = lane >> 4;

    const float4* b4 = (MODE == 0) ? (const float4*)xparam
                                   : (const float4*)g_ts;
    float4 acc = make_float4(0.f, 0.f, 0.f, 0.f);

    int e = g_row_ptr[d] + half;
    int end = g_row_ptr[d + 1];
    for (; e + 2 < end; e += 4) {
        int s0 = __ldg(&g_csr[e]);
        int s1 = __ldg(&g_csr[e + 2]);
        float4 v0 = b4[(size_t)s0 * 16 + c];
        float4 v1 = b4[(size_t)s1 * 16 + c];
        if (MODE == 0) {
            float dv0 = g_dinv[s0], dv1 = g_dinv[s1];
            acc.x += v0.x * dv0 + v1.x * dv1;
            acc.y += v0.y * dv0 + v1.y * dv1;
            acc.z += v0.z * dv0 + v1.z * dv1;
            acc.w += v0.w * dv0 + v1.w * dv1;
        } else {
            acc.x += v0.x + v1.x;
            acc.y += v0.y + v1.y;
            acc.z += v0.z + v1.z;
            acc.w += v0.w + v1.w;
        }
    }
    if (e < end) {
        int s = __ldg(&g_csr[e]);
        float4 v = b4[(size_t)s * 16 + c];
        if (MODE == 0) {
            float dv = g_dinv[s];
            acc.x += v.x * dv; acc.y += v.y * dv;
            acc.z += v.z * dv; acc.w += v.w * dv;
        } else {
            acc.x += v.x; acc.y += v.y; acc.z += v.z; acc.w += v.w;
        }
    }

    acc.x += __shfl_down_sync(0xffffffffu, acc.x, 16);
    acc.y += __shfl_down_sync(0xffffffffu, acc.y, 16);
    acc.z += __shfl_down_sync(0xffffffffu, acc.z, 16);
    acc.w += __shfl_down_sync(0xffffffffu, acc.w, 16);

    if (half == 0) {
        float dvd = g_dinv[d];
        float4 sv = b4[(size_t)d * 16 + c];
        if (MODE == 0) {
            acc.x += sv.x * dvd; acc.y += sv.y * dvd;
            acc.z += sv.z * dvd; acc.w += sv.w * dvd;
        } else {
            acc.x += sv.x; acc.y += sv.y; acc.z += sv.z; acc.w += sv.w;
        }
        acc.x *= dvd; acc.y *= dvd; acc.z *= dvd; acc.w *= dvd;
        float4* dst4 = (MODE == 0) ? (float4*)g_agg : (float4*)outparam;
        if (MODE == 1) {
            float4 bb = ((const float4*)b2)[c];
            acc.x += bb.x; acc.y += bb.y; acc.z += bb.z; acc.w += bb.w;
        }
        dst4[(size_t)d * 16 + c] = acc;
    }
}

// ---------------------------------------------------------------- fused GEMMs
// Warp handles 8 nodes.  acc pairs adjacent nodes -> fma.rn.f32x2.
// smem (floats): W1s[8192] | W2s[8192] | b1s[128] | aT[6][64*10] | hT[6][128*10]
#define FG_WARPS 6
#define FG_THREADS (FG_WARPS * 32)
#define ATS 10                       // row stride (8 used + 2 pad)
#define OFF_W2 8192
#define OFF_B1 16384
#define OFF_AT 16512
#define OFF_HT (OFF_AT + FG_WARPS * (F * ATS))
#define FG_FLOATS (OFF_HT + FG_WARPS * (HID * ATS))
#define FG_BYTES (FG_FLOATS * 4)

__global__ void __launch_bounds__(FG_THREADS, 2)
k_fused(const float* __restrict__ W1, const float* __restrict__ b1,
        const float* __restrict__ W2, int n) {
    extern __shared__ float smem[];
    float* W1s = smem;
    float* W2s = smem + OFF_W2;
    float* b1s = smem + OFF_B1;
    int tid = threadIdx.x;
    int warp = tid >> 5;
    int lane = tid & 31;

    for (int j = tid; j < (F * HID) / 4; j += FG_THREADS)
        ((float4*)W1s)[j] = ((const float4*)W1)[j];
    for (int j = tid; j < (HID * F) / 4; j += FG_THREADS)
        ((float4*)W2s)[j] = ((const float4*)W2)[j];
    for (int j = tid; j < HID; j += FG_THREADS) b1s[j] = b1[j];
    __syncthreads();

    int nbase = (blockIdx.x * FG_WARPS + warp) * 8;
    if (nbase >= n) return;
    float* aTw = smem + OFF_AT + warp * (F * ATS);
    float* hTw = smem + OFF_HT + warp * (HID * ATS);

    // stage a (transposed): aT row k holds 8 nodes' a[k]
#pragma unroll
    for (int ni = 0; ni < 8; ni++) {
        int node = nbase + ni;
        float a0 = 0.f, a1 = 0.f;
        if (node < n) {
            a0 = g_agg[(size_t)node * F + lane];
            a1 = g_agg[(size_t)node * F + 32 + lane];
        }
        aTw[lane * ATS + ni] = a0;
        aTw[(lane + 32) * ATS + ni] = a1;
    }
    __syncwarp();

    // ---- layer 1: acc[p][j] = packed (node 2p, 2p+1) at col lane+32j
    ull acc[4][4];
#pragma unroll
    for (int p = 0; p < 4; p++)
#pragma unroll
        for (int j = 0; j < 4; j++) acc[p][j] = 0ull;

#pragma unroll 4
    for (int k = 0; k < F; k++) {
        const ull* ar = (const ull*)(aTw + k * ATS);
        ull a0 = ar[0], a1 = ar[1], a2 = ar[2], a3 = ar[3];
        const float* wr = W1s + k * HID + lane;
        ull w0 = pack2(wr[0], wr[0]);
        ull w1 = pack2(wr[32], wr[32]);
        ull w2 = pack2(wr[64], wr[64]);
        ull w3 = pack2(wr[96], wr[96]);
        acc[0][0] = ffma2(a0, w0, acc[0][0]);
        acc[0][1] = ffma2(a0, w1, acc[0][1]);
        acc[0][2] = ffma2(a0, w2, acc[0][2]);
        acc[0][3] = ffma2(a0, w3, acc[0][3]);
        acc[1][0] = ffma2(a1, w0, acc[1][0]);
        acc[1][1] = ffma2(a1, w1, acc[1][1]);
        acc[1][2] = ffma2(a1, w2, acc[1][2]);
        acc[1][3] = ffma2(a1, w3, acc[1][3]);
        acc[2][0] = ffma2(a2, w0, acc[2][0]);
        acc[2][1] = ffma2(a2, w1, acc[2][1]);
        acc[2][2] = ffma2(a2, w2, acc[2][2]);
        acc[2][3] = ffma2(a2, w3, acc[2][3]);
        acc[3][0] = ffma2(a3, w0, acc[3][0]);
        acc[3][1] = ffma2(a3, w1, acc[3][1]);
        acc[3][2] = ffma2(a3, w2, acc[3][2]);
        acc[3][3] = ffma2(a3, w3, acc[3][3]);
    }

    // bias + relu -> hT (row = output col 0..127, entries = 8 nodes)
#pragma unroll
    for (int j = 0; j < 4; j++) {
        float bb = b1s[lane + 32 * j];
        float* hrow = hTw + (lane + 32 * j) * ATS;
#pragma unroll
        for (int p = 0; p < 4; p++) {
            float lo, hi;
            unpack2(acc[p][j], lo, hi);
            lo = fmaxf(lo + bb, 0.f);
            hi = fmaxf(hi + bb, 0.f);
            ((ull*)hrow)[p] = pack2(lo, hi);
        }
    }
    __syncwarp();

    // ---- layer 2: out cols lane, lane+32
    ull t0[4], t1[4];
#pragma unroll
    for (int p = 0; p < 4; p++) { t0[p] = 0ull; t1[p] = 0ull; }

#pragma unroll 2
    for (int k = 0; k < HID; k++) {
        const ull* hr = (const ull*)(hTw + k * ATS);
        ull h0 = hr[0], h1 = hr[1], h2 = hr[2], h3 = hr[3];
        float u0 = W2s[k * F + lane];
        float u1 = W2s[k * F + lane + 32];
        ull up0 = pack2(u0, u0);
        ull up1 = pack2(u1, u1);
        t0[0] = ffma2(h0, up0, t0[0]);
        t0[1] = ffma2(h1, up0, t0[1]);
        t0[2] = ffma2(h2, up0, t0[2]);
        t0[3] = ffma2(h3, up0, t0[3]);
        t1[0] = ffma2(h0, up1, t1[0]);
        t1[1] = ffma2(h1, up1, t1[1]);
        t1[2] = ffma2(h2, up1, t1[2]);
        t1[3] = ffma2(h3, up1, t1[3]);
    }

    // ts = t * dinv -> g_ts
#pragma unroll
    for (int p = 0; p < 4; p++) {
        int n0 = nbase + 2 * p;
        int n1 = n0 + 1;
        float lo0, hi0, lo1, hi1;
        unpack2(t0[p], lo0, hi0);
        unpack2(t1[p], lo1, hi1);
        if (n0 < n) {
            float dv = g_dinv[n0];
            g_ts[(size_t)n0 * F + lane] = lo0 * dv;
            g_ts[(size_t)n0 * F + 32 + lane] = lo1 * dv;
        }
        if (n1 < n) {
            float dv = g_dinv[n1];
            g_ts[(size_t)n1 * F + lane] = hi0 * dv;
            g_ts[(size_t)n1 * F + 32 + lane] = hi1 * dv;
        }
    }
}

// ---------------------------------------------------------------- launch
extern "C" void kernel_launch(void* const* d_in, const int* in_sizes, int n_in,
                              void* d_out, int out_size) {
    const float* x  = (const float*)d_in[0];
    const int* ei   = (const int*)d_in[1];   // int32 edge_index [2, E]
    const float* W1 = (const float*)d_in[2];
    const float* b1 = (const float*)d_in[3];
    const float* W2 = (const float*)d_in[4];
    const float* b2 = (const float*)d_in[5];
    float* out      = (float*)d_out;

    int n = in_sizes[0] / F;   // 100000
    int E = in_sizes[1] / 2;   // 1600000
    const int* src = ei;
    const int* dst = ei + E;

    cudaFuncSetAttribute(k_fused, cudaFuncAttributeMaxDynamicSharedMemorySize,
                         FG_BYTES);

    int nbN = (n + 255) / 256;
    int nbE = (E + 255) / 256;
    int nbScan = (n + SCAN_BS - 1) / SCAN_BS;

    // CSR build + dinv
    k_zero<<<nbN, 256>>>(n);
    k_hist<<<nbE, 256>>>(dst, E);
    k_scan1<<<nbScan, SCAN_BS>>>(n);
    k_scan2<<<1, 128>>>(nbScan);
    k_scan3<<<nbN, 256>>>(n, E);
    k_permute<<<nbE, 256>>>(src, dst, E);

    // layer 1 aggregation (reads x, scales by dinv[s] on the fly)
    int gth_blocks = (n * 32 + 255) / 256;
    k_gather<0><<<gth_blocks, 256>>>(x, nullptr, nullptr, n);

    // fused double GEMM
    int fg_blocks = ((n + 7) / 8 + FG_WARPS - 1) / FG_WARPS;
    k_fused<<<fg_blocks, FG_THREADS, FG_BYTES>>>(W1, b1, W2, n);

    // layer 2 aggregation + epilogue
    k_gather<1><<<gth_blocks, 256>>>(nullptr, b2, out, n);
}